// round 12
// baseline (speedup 1.0000x reference)
#include <cuda_runtime.h>
#include <cuda_bf16.h>

// NearestMatcher: B rows, N=16 queries, T=8 targets.
//   tgt = (targets==0) ? 1e6 : targets
//   indices = argmin_t |pd - tgt| (first on ties)
//   C = min_dist - sigmoid(logits); labels[i]=1 iff C_i is the stable-min of its group
//
// Dedup via per-thread private 8-slot smem group-min table of EXACT sortable-uint
// cost keys. Layout tbl[g][128]: word index g*128+tid -> bank == lane for every g
// pattern => zero conflicts. Thread-private => no synchronization anywhere.
// R11: group ids packed 4b x16 into two uints (frees ~14 regs), launch_bounds
// (128,9) for 36 warps/SM, and software-pipelined input loads for MLP.

#define NQ 16
#define NT 8
#define BIGV 1000000.0f

// order-preserving float->uint bijection (exact; handles negatives)
__device__ __forceinline__ unsigned sortable(float f) {
    unsigned u = __float_as_uint(f);
    int s = ((int)u) >> 31;                 // 0 or ~0
    return u ^ ((unsigned)s | 0x80000000u); // SHF + LOP3
}

template<bool FULL>
__global__ __launch_bounds__(128, 9)
void nearest_matcher_kernel(const float4* __restrict__ lg4,
                            const float4* __restrict__ pd4,
                            const float4* __restrict__ tg4,
                            float* __restrict__ out,
                            int B)
{
    __shared__ unsigned tbl_s[NT][128];
    unsigned* tbl = &tbl_s[0][threadIdx.x];   // slot g lives at tbl[g*128]

    int b = blockIdx.x * blockDim.x + threadIdx.x;
    if (b >= B) return;

    // ---- init private group-min table (conflict-free STS) ----
#pragma unroll
    for (int g = 0; g < NT; g++) tbl[g * 128] = 0xFFFFFFFFu;

    // ---- targets: 2x LDG.128, sentinel nulls (exact compare to +0) ----
    float4 t0 = tg4[2 * b + 0];
    float4 t1 = tg4[2 * b + 1];
    float tgt[NT] = { t0.x, t0.y, t0.z, t0.w, t1.x, t1.y, t1.z, t1.w };
#pragma unroll
    for (int t = 0; t < NT; t++)
        tgt[t] = (tgt[t] == 0.0f) ? BIGV : tgt[t];

    unsigned K[NQ];                 // exact sortable cost keys
    unsigned gp0 = 0u, gp1 = 0u;    // group ids, 4-bit fields (q0..7 | q8..15)

    // ---- software-pipelined chunk loop: load c+1 while computing c ----
    float4 pv = pd4[4 * b + 0];
    float4 lv = lg4[4 * b + 0];
#pragma unroll
    for (int c = 0; c < 4; c++) {
        float4 pv_n, lv_n;
        if (c < 3) { pv_n = pd4[4 * b + c + 1]; lv_n = lg4[4 * b + c + 1]; }

        float pc[4] = { pv.x, pv.y, pv.z, pv.w };
        float lc[4] = { lv.x, lv.y, lv.z, lv.w };
        int gi[4];
#pragma unroll
        for (int q = 0; q < 4; q++) {
            int n = 4 * c + q;
            float p = pc[q];
            float d[NT];
#pragma unroll
            for (int t = 0; t < NT; t++)
                d[t] = p - tgt[t];            // FADD; |.| folds as modifier below

            // balanced EXACT argmin tree: FMNMX value path + FSETP/SEL index
            // path. Strict < keeps LOWER index on exact ties == jnp.argmin.
            float m01 = fminf(fabsf(d[0]), fabsf(d[1]));
            int   i01 = (fabsf(d[1]) < fabsf(d[0])) ? 1 : 0;
            float m23 = fminf(fabsf(d[2]), fabsf(d[3]));
            int   i23 = (fabsf(d[3]) < fabsf(d[2])) ? 3 : 2;
            float m45 = fminf(fabsf(d[4]), fabsf(d[5]));
            int   i45 = (fabsf(d[5]) < fabsf(d[4])) ? 5 : 4;
            float m67 = fminf(fabsf(d[6]), fabsf(d[7]));
            int   i67 = (fabsf(d[7]) < fabsf(d[6])) ? 7 : 6;
            float m03 = fminf(m01, m23);  int i03 = (m23 < m01) ? i23 : i01;
            float m47 = fminf(m45, m67);  int i47 = (m67 < m45) ? i67 : i45;
            float m   = fminf(m03, m47);  int g   = (m47 < m03) ? i47 : i03;

            // exact reference cost: C = min_dist - sigmoid(logit)
            float s = __fdividef(1.0f, 1.0f + __expf(-lc[q]));
            float C = m - s;

            unsigned w = sortable(C);
            K[n] = w;
            gi[q] = g;
            if (n < 8) gp0 |= (unsigned)g << (n * 4);
            else       gp1 |= (unsigned)g << ((n - 8) * 4);

            // private scatter-min (LDS+IMNMX+STS, bank==lane, conflict-free)
            unsigned cur = tbl[g * 128];
            tbl[g * 128] = umin(cur, w);
        }

        if (FULL) {
            // indices final for this chunk: store now (overlaps remaining work)
            reinterpret_cast<float4*>(out)[4 * (size_t)b + c] =
                make_float4((float)gi[0], (float)gi[1], (float)gi[2], (float)gi[3]);
        } else {
            reinterpret_cast<int4*>(out)[4 * (size_t)b + c] =
                make_int4(gi[0], gi[1], gi[2], gi[3]);
        }

        pv = pv_n; lv = lv_n;
    }

    if (FULL) {
        // ---- labels: query n wins iff its key IS its group's minimum ----
        float lf[NQ];
#pragma unroll
        for (int n = 0; n < NQ; n++) {
            unsigned g = (n < 8) ? ((gp0 >> (n * 4)) & 7u)
                                 : ((gp1 >> ((n - 8) * 4)) & 7u);
            lf[n] = (tbl[g * 128] == K[n]) ? 1.0f : 0.0f;
        }

        float4* ol = reinterpret_cast<float4*>(out + (size_t)B * NQ) + 4 * (size_t)b;
#pragma unroll
        for (int q = 0; q < 4; q++)
            ol[q] = make_float4(lf[4 * q + 0], lf[4 * q + 1],
                                lf[4 * q + 2], lf[4 * q + 3]);
    }
}

extern "C" void kernel_launch(void* const* d_in, const int* in_sizes, int n_in,
                              void* d_out, int out_size)
{
    // metadata order: pred_logits [B,16], pred_disp [B,16], targets [B,8]
    const float4* lg = reinterpret_cast<const float4*>(d_in[0]);
    const float4* pd = reinterpret_cast<const float4*>(d_in[1]);
    const float4* tg = reinterpret_cast<const float4*>(d_in[2]);
    int B = in_sizes[0] / NQ;

    const int threads = 128;
    const int blocks  = (B + threads - 1) / threads;

    if ((long long)out_size >= 2LL * B * NQ) {
        nearest_matcher_kernel<true><<<blocks, threads>>>(lg, pd, tg, (float*)d_out, B);
    } else {
        nearest_matcher_kernel<false><<<blocks, threads>>>(lg, pd, tg, (float*)d_out, B);
    }
}